// round 17
// baseline (speedup 1.0000x reference)
#include <cuda_runtime.h>
#include <math.h>

#define BATCH    16384
#define MAZE_LEN 3844
#define NWARPS   2048          // each warp does rows w + j*2048, j=0..7

// Math: -log(clip(chain-AND, e^-90)) == min(log(S - 127), 90),
//   S = sum of reciprocals of the 120 gathered columns per row
//   (+8 dummy rcp(1)=1 from inactive mid lanes, folded into the 127).
// Loads: sector-packed scalar gather via __ldg (.nc); 37 lines/row is the
//   irreducible line count. This round: 8 rows/warp (32 outstanding loads
//   per lane), 256 CTAs -> half the per-CTA atomics and drain events.

__device__ __forceinline__ float fast_rcp(float x) {
    float r;
    asm("rcp.approx.ftz.f32 %0, %1;" : "=f"(r) : "f"(x));
    return r;
}

// Fold 4 reciprocals into one MUFU.RCP.
__device__ __forceinline__ float fold4(float h, float t, float m0, float m1) {
    const float a   = h * t;
    const float b   = m0 * m1;
    const float num = (h + t) * b + (m0 + m1) * a;
    return num * fast_rcp(a * b);
}

__global__ __launch_bounds__(256)
void fuzzy_chain_kernel(const float* __restrict__ maze, float* __restrict__ out)
{
    const int warp_local  = threadIdx.x >> 5;                 // 0..7
    const int warp_global = blockIdx.x * 8 + warp_local;
    const int lane        = threadIdx.x & 31;

    // ---- per-lane scalar indices (shared by all 8 rows) ------------------
    int h_i = 4 * lane + 1;
    if (lane == 0) h_i = 1;
    if (lane == 1) h_i = 6;

    int t_i = 3717 + 4 * lane;
    if (lane == 29) t_i = 3721;                   // duplicate 3721
    if (lane == 30) t_i = 3839;
    if (lane == 31) t_i = 3841;

    const int k     = lane >> 1;
    const int comp  = lane & 1;
    const int p1    = 16 + k;
    const bool act1 = (p1 < 28);
    const int m0_i  = 124 * k + 245 + 4 * comp;
    const int m1_i  = 124 * (act1 ? p1 : 27) + 245 + 4 * comp;

    // ---- 8 striped rows; front-batch all 32 loads, then fold -------------
    float s[8];
    const float* __restrict__ base = maze + (size_t)warp_global * MAZE_LEN;

    float hv[8], tv[8], av[8], bv[8];
    #pragma unroll
    for (int j = 0; j < 8; j++) {
        const float* __restrict__ r = base + (size_t)j * NWARPS * MAZE_LEN;
        hv[j] = __ldg(r + h_i);
        tv[j] = __ldg(r + t_i);
        av[j] = __ldg(r + m0_i);
        bv[j] = __ldg(r + m1_i);
    }

    #pragma unroll
    for (int j = 0; j < 8; j++) {
        const float b = act1 ? bv[j] : 1.0f;      // dummy -> rcp(1)=1, in constant
        s[j] = fold4(hv[j], tv[j], av[j], b);
    }

    // ---- warp reduction of all 8 rows' S ---------------------------------
    #pragma unroll
    for (int off = 16; off > 0; off >>= 1) {
        #pragma unroll
        for (int j = 0; j < 8; j++)
            s[j] += __shfl_xor_sync(0xffffffffu, s[j], off);
    }

    __shared__ float warp_vals[8];
    if (lane == 0) {
        // x==0 -> inf -> log(inf)=inf -> fminf -> 90; two zeros -> NaN ->
        // fminf(NaN,90)=90 (matches the reference clip exactly).
        float v = 0.0f;
        #pragma unroll
        for (int j = 0; j < 8; j++)
            v += fminf(logf(s[j] - 127.0f), 90.0f);
        warp_vals[warp_local] = v;
    }
    __syncthreads();

    if (threadIdx.x == 0) {
        float t = 0.0f;
        #pragma unroll
        for (int i = 0; i < 8; i++) t += warp_vals[i];
        atomicAdd(out, t * (1.0f / (float)BATCH));   // exact power-of-two scale
    }
}

extern "C" void kernel_launch(void* const* d_in, const int* in_sizes, int n_in,
                              void* d_out, int out_size)
{
    const float* maze = (const float*)d_in[0];
    float*       out  = (float*)d_out;

    cudaMemsetAsync(out, 0, sizeof(float), 0);      // overlaps kernel ramp

    const int blocks = NWARPS / 8;                  // 256 CTAs, 256 threads each
    fuzzy_chain_kernel<<<blocks, 256>>>(maze, out);
}